// round 13
// baseline (speedup 1.0000x reference)
#include <cuda_runtime.h>

#define Nn 2048
#define Ee 65536

// ---------------- scratch (device globals; no allocations) ----------------
__device__ __align__(16) float g_feat[Nn*320];     // [x | h1 | h2]
__device__ __align__(16) float g_xW[Nn*128];       // 512B line-aligned rows
__device__ __align__(16) float g_xr[Nn];
__device__ __align__(16) float g_S[Nn*128];
__device__ __align__(16) float g_ab[Nn*40];        // zeroed in setup (split-K atomics)
__device__ __align__(16) float g_W1p[40*320];
__device__ __align__(16) float g_B0p[129*64];
__device__ __align__(16) float g_B1p[129*128];
__device__ __align__(16) float g_w1e[256];
__device__ __align__(16) float2 g_edge[Ee];        // CSR payload: (src bits, edge_attr)
__device__ int g_deg[Nn];                          // invariant: zero (restored by scan)
__device__ int g_off[Nn+1];
__device__ int g_cur[Nn];

__device__ __forceinline__ float lrelu(float x) { return x > 0.f ? x : 0.01f*x; }

__device__ __forceinline__ float* sel_ptr(int s) {
  switch (s) {
    case 0: return g_feat;
    case 1: return g_S;
    case 2: return g_xW;
    case 3: return g_W1p;
    case 4: return g_B0p;
    case 5: return g_B1p;
    case 6: return g_ab;
    default: return nullptr;
  }
}

// ---------------- fused setup: embed + packs + hist + ab-zero ----------------
__global__ void k_setup(const int* __restrict__ ids, const float* __restrict__ emb,
                        const float* __restrict__ W1,
                        const float* __restrict__ l0_lin1, const float* __restrict__ l1_lin1,
                        const float* __restrict__ l0_attr, const float* __restrict__ l1_attr,
                        const int* __restrict__ edst) {
  int b = blockIdx.x, tid = threadIdx.x;
  if (b < 512) {
    int node = b*4 + (tid >> 6);
    int col = tid & 63;
    g_feat[node*320 + col] = emb[ids[node]*64 + col];
  } else if (b < 562) {
    int i = (b-512)*256 + tid;
    if (i < 40*320) {
      int r = i/320, c = i - r*320;
      g_W1p[i] = (r < 20) ? W1[r*640 + c] : W1[(r-20)*640 + 320 + c];
    }
  } else if (b == 562) {
    if (tid < 128) {
      g_w1e[tid]       = l0_lin1[tid*65  + 64];
      g_w1e[128 + tid] = l1_lin1[tid*129 + 128];
    }
  } else if (b < 596) {
    int i = (b-563)*256 + tid;
    if (i < 129*64) {
      int r = i >> 6, c = i & 63;
      g_B0p[i] = (r < 128) ? l0_lin1[r*65 + c] : l0_attr[c];
    }
  } else if (b < 661) {
    int i = (b-596)*256 + tid;
    if (i < 129*128) {
      int r = i >> 7, c = i & 127;
      g_B1p[i] = (r < 128) ? l1_lin1[r*129 + c] : l1_attr[c];
    }
  } else if (b < 917) {
    int e = (b-661)*256 + tid;
    atomicAdd(&g_deg[edst[e]], 1);
  } else {
    g_ab[(b-917)*256 + tid] = 0.f;     // 320 blocks: 81920 floats
  }
}

// ---------------- scan (256 threads), restores g_deg=0 ----------------
__device__ void dev_scan() {
  __shared__ int sw[8];
  int tid = threadIdx.x;
  int base = tid*8;
  int v[8], run = 0;
  #pragma unroll
  for (int i = 0; i < 8; i++) { v[i] = g_deg[base+i]; run += v[i]; }
  int lane = tid & 31, wid = tid >> 5;
  int incl = run;
  #pragma unroll
  for (int o = 1; o < 32; o <<= 1) {
    int u = __shfl_up_sync(0xffffffffu, incl, o);
    if (lane >= o) incl += u;
  }
  if (lane == 31) sw[wid] = incl;
  __syncthreads();
  if (tid == 0) {
    int acc = 0;
    #pragma unroll
    for (int w = 0; w < 8; w++) { int x = sw[w]; sw[w] = acc; acc += x; }
  }
  __syncthreads();
  int off = sw[wid] + incl - run;
  #pragma unroll
  for (int i = 0; i < 8; i++) {
    g_off[base+i] = off; g_cur[base+i] = off;
    off += v[i];
    g_deg[base+i] = 0;
  }
  if (tid == 0) g_off[2048] = Ee;
}

// ---------------- double-buffered 64x64 GEMM: C = act(A @ B^T + bias) --------
// splitXr: route output column 128 to g_xr (xW GEMMs write 512B-aligned rows)
template<int ACT, int ATOMIC>
__global__ void __launch_bounds__(256)
k_gemm(int Asel, int aoff, int lda, int Bsel, const float* __restrict__ Bext, int ldb,
       const float* __restrict__ bias, int Csel, int coff, int ldc,
       int Ncols, int K, int nMt, int ntiles, int withScan, int splitXr) {
  if (withScan && (int)blockIdx.x == ntiles) { dev_scan(); return; }
  if ((int)blockIdx.x >= ntiles) return;
  __shared__ __align__(16) float As[2][32][68];
  __shared__ __align__(16) float Bs[2][32][68];
  int koff = blockIdx.y * 64;
  const float* A = sel_ptr(Asel) + aoff + koff;
  const float* B = (Bsel >= 0 ? sel_ptr(Bsel) : Bext) + koff;
  float* C = sel_ptr(Csel) + coff;
  int tid = threadIdx.x;
  int tx = tid & 15, ty = tid >> 4;
  int tile = blockIdx.x;
  int m0 = (tile % nMt)*64, n0 = (tile / nMt)*64;
  int lr = tid >> 3;            // 0..31
  int ca = (tid & 7)*4;
  int rn0 = n0 + lr, rn1 = rn0 + 32;
  float4 ra0, ra1, rb0, rb1;
  const float4 z4 = make_float4(0.f,0.f,0.f,0.f);

  #define LDG_CHUNK(k0)                                                        \
    ra0 = *(const float4*)&A[(m0+lr)*lda + (k0) + ca];                         \
    ra1 = *(const float4*)&A[(m0+lr+32)*lda + (k0) + ca];                      \
    rb0 = (rn0 < Ncols) ? *(const float4*)&B[rn0*ldb + (k0) + ca] : z4;        \
    rb1 = (rn1 < Ncols) ? *(const float4*)&B[rn1*ldb + (k0) + ca] : z4;

  #define STS_CHUNK(buf)                                                       \
    As[buf][ca+0][lr] = ra0.x; As[buf][ca+1][lr] = ra0.y;                      \
    As[buf][ca+2][lr] = ra0.z; As[buf][ca+3][lr] = ra0.w;                      \
    As[buf][ca+0][lr+32] = ra1.x; As[buf][ca+1][lr+32] = ra1.y;                \
    As[buf][ca+2][lr+32] = ra1.z; As[buf][ca+3][lr+32] = ra1.w;                \
    Bs[buf][ca+0][lr] = rb0.x; Bs[buf][ca+1][lr] = rb0.y;                      \
    Bs[buf][ca+2][lr] = rb0.z; Bs[buf][ca+3][lr] = rb0.w;                      \
    Bs[buf][ca+0][lr+32] = rb1.x; Bs[buf][ca+1][lr+32] = rb1.y;                \
    Bs[buf][ca+2][lr+32] = rb1.z; Bs[buf][ca+3][lr+32] = rb1.w;

  float acc[4][4] = {};
  int nc = K/32;
  LDG_CHUNK(0); STS_CHUNK(0);
  __syncthreads();
  for (int c = 0; c < nc; c++) {
    if (c+1 < nc) { LDG_CHUNK((c+1)*32); }
    int buf = c & 1;
    #pragma unroll
    for (int k = 0; k < 32; k++) {
      float4 a4 = *(const float4*)&As[buf][k][ty*4];
      float4 b4 = *(const float4*)&Bs[buf][k][tx*4];
      acc[0][0] += a4.x*b4.x; acc[0][1] += a4.x*b4.y; acc[0][2] += a4.x*b4.z; acc[0][3] += a4.x*b4.w;
      acc[1][0] += a4.y*b4.x; acc[1][1] += a4.y*b4.y; acc[1][2] += a4.y*b4.z; acc[1][3] += a4.y*b4.w;
      acc[2][0] += a4.z*b4.x; acc[2][1] += a4.z*b4.y; acc[2][2] += a4.z*b4.z; acc[2][3] += a4.z*b4.w;
      acc[3][0] += a4.w*b4.x; acc[3][1] += a4.w*b4.y; acc[3][2] += a4.w*b4.z; acc[3][3] += a4.w*b4.w;
    }
    if (c+1 < nc) { STS_CHUNK((c+1)&1); }
    __syncthreads();
  }
  #pragma unroll
  for (int i = 0; i < 4; i++) {
    int mm = m0 + ty*4 + i;
    #pragma unroll
    for (int j = 0; j < 4; j++) {
      int nn = n0 + tx*4 + j;
      if (nn < Ncols) {
        float v = acc[i][j];
        if (ATOMIC) {
          atomicAdd(&C[mm*ldc + nn], v);
        } else {
          if (bias) v += bias[nn];
          if (ACT) v = fmaxf(v, 0.f);
          if (splitXr && nn == 128) g_xr[mm] = v;
          else C[mm*ldc + nn] = v;
        }
      }
    }
  }
  #undef LDG_CHUNK
  #undef STS_CHUNK
}

// ---------------- CSR scatter with combined payload ----------------
__global__ void k_scatter(const int* __restrict__ esrc, const int* __restrict__ edst,
                          const float* __restrict__ eattr) {
  int e = blockIdx.x*256 + threadIdx.x;
  int p = atomicAdd(&g_cur[edst[e]], 1);
  g_edge[p] = make_float2(__int_as_float(esrc[e]), eattr[e]);
}

// ---------------- aggregation: sub-warp groups (4 edges/warp-iter) -----------
// Block = node (grid 2048), 8 warps. Warp = 4 edge-groups x 8 lanes; each lane
// owns 16 cols (4 float4 @ stride 8). Dot reduce = 3 shfl within 8 lanes
// (serves all 4 edges at once); groups combined by a 2-step butterfly ONCE at
// the end. Gather: each load instruction covers exactly 4 x 128B lines.
__global__ void __launch_bounds__(256)
k_aggr(int w1off, const float* __restrict__ attl) {
  __shared__ float4 sh_w[32], sh_a[32];
  __shared__ float4 red[8][32];
  __shared__ float dred[8];
  int tid = threadIdx.x;
  int w = tid >> 5, lane = tid & 31;
  int g = lane >> 3, l8 = lane & 7;
  int n = blockIdx.x;
  if (tid < 32) {
    sh_w[tid] = ((const float4*)(g_w1e + w1off))[tid];
    sh_a[tid] = ((const float4*)attl)[tid];
  }
  __syncthreads();
  int begin = g_off[n], cnt = g_off[n+1] - begin;
  const float4* xw4 = (const float4*)g_xW;
  float xr = g_xr[n];
  float4 A0 = {0,0,0,0}, A1 = {0,0,0,0}, A2 = {0,0,0,0}, A3 = {0,0,0,0};
  float den = 0.f;
  float4 W0 = sh_w[l8], W1_ = sh_w[8+l8], W2_ = sh_w[16+l8], W3 = sh_w[24+l8];
  float4 V0 = sh_a[l8], V1 = sh_a[8+l8], V2 = sh_a[16+l8], V3 = sh_a[24+l8];

  for (int j0 = w*4; j0 < cnt; j0 += 32) {
    int eidx = j0 + g;
    bool valid = eidx < cnt;
    float2 ee = g_edge[begin + (valid ? eidx : cnt - 1)];
    int src = __float_as_int(ee.x);
    float ea = ee.y;
    const float4* row = xw4 + src*32 + l8;
    float4 x0 = row[0], x1 = row[8], x2 = row[16], x3 = row[24];
    float4 h0, h1, h2, h3;
    h0.x = lrelu(x0.x + ea*W0.x); h0.y = lrelu(x0.y + ea*W0.y);
    h0.z = lrelu(x0.z + ea*W0.z); h0.w = lrelu(x0.w + ea*W0.w);
    h1.x = lrelu(x1.x + ea*W1_.x); h1.y = lrelu(x1.y + ea*W1_.y);
    h1.z = lrelu(x1.z + ea*W1_.z); h1.w = lrelu(x1.w + ea*W1_.w);
    h2.x = lrelu(x2.x + ea*W2_.x); h2.y = lrelu(x2.y + ea*W2_.y);
    h2.z = lrelu(x2.z + ea*W2_.z); h2.w = lrelu(x2.w + ea*W2_.w);
    h3.x = lrelu(x3.x + ea*W3.x); h3.y = lrelu(x3.y + ea*W3.y);
    h3.z = lrelu(x3.z + ea*W3.z); h3.w = lrelu(x3.w + ea*W3.w);
    float pp = h0.x*V0.x + h0.y*V0.y + h0.z*V0.z + h0.w*V0.w
             + h1.x*V1.x + h1.y*V1.y + h1.z*V1.z + h1.w*V1.w
             + h2.x*V2.x + h2.y*V2.y + h2.z*V2.z + h2.w*V2.w
             + h3.x*V3.x + h3.y*V3.y + h3.z*V3.z + h3.w*V3.w;
    pp += __shfl_xor_sync(0xffffffffu, pp, 4);
    pp += __shfl_xor_sync(0xffffffffu, pp, 2);
    pp += __shfl_xor_sync(0xffffffffu, pp, 1);
    float ev = valid ? __expf(lrelu(pp + xr)) : 0.f;
    A0.x += ev*h0.x; A0.y += ev*h0.y; A0.z += ev*h0.z; A0.w += ev*h0.w;
    A1.x += ev*h1.x; A1.y += ev*h1.y; A1.z += ev*h1.z; A1.w += ev*h1.w;
    A2.x += ev*h2.x; A2.y += ev*h2.y; A2.z += ev*h2.z; A2.w += ev*h2.w;
    A3.x += ev*h3.x; A3.y += ev*h3.y; A3.z += ev*h3.z; A3.w += ev*h3.w;
    den += ev;
  }
  // combine the 4 edge-groups (lanes xor 8, 16 hold the same 16 columns)
  #pragma unroll
  for (int s = 8; s <= 16; s <<= 1) {
    A0.x += __shfl_xor_sync(0xffffffffu, A0.x, s); A0.y += __shfl_xor_sync(0xffffffffu, A0.y, s);
    A0.z += __shfl_xor_sync(0xffffffffu, A0.z, s); A0.w += __shfl_xor_sync(0xffffffffu, A0.w, s);
    A1.x += __shfl_xor_sync(0xffffffffu, A1.x, s); A1.y += __shfl_xor_sync(0xffffffffu, A1.y, s);
    A1.z += __shfl_xor_sync(0xffffffffu, A1.z, s); A1.w += __shfl_xor_sync(0xffffffffu, A1.w, s);
    A2.x += __shfl_xor_sync(0xffffffffu, A2.x, s); A2.y += __shfl_xor_sync(0xffffffffu, A2.y, s);
    A2.z += __shfl_xor_sync(0xffffffffu, A2.z, s); A2.w += __shfl_xor_sync(0xffffffffu, A2.w, s);
    A3.x += __shfl_xor_sync(0xffffffffu, A3.x, s); A3.y += __shfl_xor_sync(0xffffffffu, A3.y, s);
    A3.z += __shfl_xor_sync(0xffffffffu, A3.z, s); A3.w += __shfl_xor_sync(0xffffffffu, A3.w, s);
    den  += __shfl_xor_sync(0xffffffffu, den, s);
  }
  if (g == 0) {
    red[w][l8]      = A0;
    red[w][8 + l8]  = A1;
    red[w][16 + l8] = A2;
    red[w][24 + l8] = A3;
  }
  if (lane == 0) dred[w] = den;
  __syncthreads();
  if (w == 0) {
    float d = dred[0]+dred[1]+dred[2]+dred[3]+dred[4]+dred[5]+dred[6]+dred[7];
    float inv = 1.f/(d + 1e-16f);
    int f = lane & 3, q = lane >> 2;          // (f, q) -> float4 index f*8+q
    float4 r = red[0][f*8+q];
    #pragma unroll
    for (int s = 1; s < 8; s++) {
      float4 o = red[s][f*8+q];
      r.x += o.x; r.y += o.y; r.z += o.z; r.w += o.w;
    }
    ((float4*)g_S)[n*32 + f*8 + q] = make_float4(r.x*inv, r.y*inv, r.z*inv, r.w*inv);
  }
}

// ---------------- fused pairwise MLP + masked row softmax (f32x2, reg logits) -
__global__ void __launch_bounds__(256)
k_final(const float* __restrict__ b1, const float* __restrict__ W2,
        const float* __restrict__ b2, const float* __restrict__ m,
        float* __restrict__ out) {
  __shared__ unsigned long long ash2[8][10];       // packed (a+b1) col pairs
  __shared__ unsigned long long w2sh[10];
  __shared__ float rowM[8], rowInv[8];
  __shared__ __align__(16) float btile[256][22];   // stride 22 -> aligned b64; reused for reduce
  int tid = threadIdx.x;
  int i0 = blockIdx.x * 8;
  if (tid < 80) {
    int r = tid/10, cp = tid - r*10;
    float a0 = g_ab[(i0+r)*40 + 2*cp]   + b1[2*cp];
    float a1 = g_ab[(i0+r)*40 + 2*cp+1] + b1[2*cp+1];
    asm("mov.b64 %0, {%1, %2};" : "=l"(ash2[r][cp]) : "f"(a0), "f"(a1));
  }
  if (tid < 10) {
    asm("mov.b64 %0, {%1, %2};" : "=l"(w2sh[tid]) : "f"(W2[2*tid]), "f"(W2[2*tid+1]));
  }
  float b2v = b2[0];
  float lreg[8][8];                                // [tile][row] raw logits
  float omax[8], osum[8];
  #pragma unroll
  for (int r = 0; r < 8; r++) { omax[r] = -1e30f; osum[r] = 0.f; }
  __syncthreads();
  unsigned long long wr[10];
  #pragma unroll
  for (int cp = 0; cp < 10; cp++) wr[cp] = w2sh[cp];

  #pragma unroll
  for (int t = 0; t < 8; t++) {
    int jt = t*256;
    __syncthreads();
    #pragma unroll
    for (int u = 0; u < 20; u++) {
      int l = u*256 + tid;
      int tt = l / 20, c = l - tt*20;
      btile[tt][c] = g_ab[(jt+tt)*40 + 20 + c];
    }
    __syncthreads();
    unsigned long long bl2[10];
    #pragma unroll
    for (int cp = 0; cp < 10; cp++)
      bl2[cp] = *(const unsigned long long*)&btile[tid][2*cp];
    int j = jt + tid;
    #pragma unroll
    for (int r = 0; r < 8; r++) {
      unsigned long long acc2 = 0ULL;      // (0.f, 0.f)
      #pragma unroll
      for (int cp = 0; cp < 10; cp++) {
        unsigned long long s;
        asm("add.rn.f32x2 %0, %1, %2;" : "=l"(s) : "l"(ash2[r][cp]), "l"(bl2[cp]));
        float lo, hi;
        asm("mov.b64 {%0, %1}, %2;" : "=f"(lo), "=f"(hi) : "l"(s));
        lo = fmaxf(lo, 0.f); hi = fmaxf(hi, 0.f);
        asm("mov.b64 %0, {%1, %2};" : "=l"(s) : "f"(lo), "f"(hi));
        asm("fma.rn.f32x2 %0, %1, %2, %3;" : "=l"(acc2) : "l"(s), "l"(wr[cp]), "l"(acc2));
      }
      float alo, ahi;
      asm("mov.b64 {%0, %1}, %2;" : "=f"(alo), "=f"(ahi) : "l"(acc2));
      float lv = (alo + ahi + b2v) * m[(size_t)(i0+r)*Nn + j];
      lreg[t][r] = lv;
      float nm = fmaxf(omax[r], lv);
      osum[r] = osum[r]*__expf(omax[r]-nm) + __expf(lv-nm);
      omax[r] = nm;
    }
  }
  // (max,sum) merge: smem transpose + warp reduction (2 syncs)
  __syncthreads();
  float2* pr = (float2*)btile;
  #pragma unroll
  for (int r = 0; r < 8; r++) pr[r*256 + tid] = make_float2(omax[r], osum[r]);
  __syncthreads();
  int w = tid >> 5, lane = tid & 31;
  if (w < 8) {
    float M = -1e30f, S = 0.f;
    #pragma unroll
    for (int i = 0; i < 8; i++) {
      float2 v = pr[w*256 + lane + i*32];
      float nm = fmaxf(M, v.x);
      S = S*__expf(M-nm) + v.y*__expf(v.x-nm);
      M = nm;
    }
    #pragma unroll
    for (int s = 16; s > 0; s >>= 1) {
      float oM = __shfl_xor_sync(0xffffffffu, M, s);
      float oS = __shfl_xor_sync(0xffffffffu, S, s);
      float nm = fmaxf(M, oM);
      S = S*__expf(M-nm) + oS*__expf(oM-nm);
      M = nm;
    }
    if (lane == 0) { rowM[w] = M; rowInv[w] = 1.f/S; }
  }
  __syncthreads();
  #pragma unroll
  for (int t = 0; t < 8; t++) {
    int j = t*256 + tid;
    #pragma unroll
    for (int r = 0; r < 8; r++) {
      out[(size_t)(i0+r)*Nn + j] = __expf(lreg[t][r] - rowM[r]) * rowInv[r];
    }
  }
}

// ---------------- driver ----------------
extern "C" void kernel_launch(void* const* d_in, const int* in_sizes, int n_in,
                              void* d_out, int out_size) {
  const int*   node_ids = (const int*)  d_in[0];
  const int*   eidx     = (const int*)  d_in[1];
  const float* eattr    = (const float*)d_in[2];
  const float* m        = (const float*)d_in[3];
  const float* emb      = (const float*)d_in[4];
  const float* l0_lin1  = (const float*)d_in[5];
  const float* l0_lin2  = (const float*)d_in[6];
  const float* l0_attl  = (const float*)d_in[7];
  const float* l0_attr  = (const float*)d_in[8];
  const float* l0_bias  = (const float*)d_in[9];
  const float* l1_lin1  = (const float*)d_in[10];
  const float* l1_lin2  = (const float*)d_in[11];
  const float* l1_attl  = (const float*)d_in[12];
  const float* l1_attr  = (const float*)d_in[13];
  const float* l1_bias  = (const float*)d_in[14];
  const float* W1       = (const float*)d_in[15];
  const float* b1       = (const float*)d_in[16];
  const float* W2       = (const float*)d_in[17];
  const float* b2       = (const float*)d_in[18];
  float* out = (float*)d_out;
  const int* esrc = eidx;
  const int* edst = eidx + Ee;

  k_setup<<<1237, 256>>>(node_ids, emb, W1, l0_lin1, l1_lin1, l0_attr, l1_attr, edst);

  // xW0 (96 tiles, col 128 -> g_xr) + CSR scan (block 96)
  k_gemm<0,0><<<97, 256>>>(0, 0, 320, 4, nullptr, 64, nullptr, 2, 0, 128,
                           129, 64, 32, 96, 1, 1);
  k_scatter<<<Ee/256, 256>>>(esrc, edst, eattr);
  k_aggr<<<Nn, 256>>>(0, l0_attl);
  k_gemm<1,0><<<64, 256>>>(1, 0, 128, -1, l0_lin2, 128, l0_bias, 0, 64, 320,
                           128, 128, 32, 64, 0, 0);       // h1 -> feat cols 64..191
  k_gemm<0,0><<<96, 256>>>(0, 64, 320, 5, nullptr, 128, nullptr, 2, 0, 128,
                           129, 128, 32, 96, 0, 1);       // xW1 (col 128 -> g_xr)
  k_aggr<<<Nn, 256>>>(128, l1_attl);
  k_gemm<1,0><<<64, 256>>>(1, 0, 128, -1, l1_lin2, 128, l1_bias, 0, 192, 320,
                           128, 128, 32, 64, 0, 0);       // h2 -> feat cols 192..319
  // ab split-K: grid (32 Mtiles, 5 K-chunks), atomicAdd into zeroed g_ab
  k_gemm<0,1><<<dim3(32, 5), 256>>>(0, 0, 320, 3, nullptr, 320, nullptr, 6, 0, 40,
                                    40, 64, 32, 32, 0, 0);
  k_final<<<Nn/8, 256>>>(b1, W2, b2, m, out);
}